// round 8
// baseline (speedup 1.0000x reference)
#include <cuda_runtime.h>
#include <cuda_bf16.h>
#include <math.h>

#define NT     365
#define NGRID  2048
#define NX     16
#define NH     256
#define G4     1024              // 4*NH
#define K2     512               // combined k = NH (h) + NH (x0)
#define NROWS  (NT * NGRID)      // 747520
#define KS16   32                // K2/16 k-tiles
#define MROWS  32                // rows per CTA (two m16 groups share B fragments)
#define ROW_BF 528               // act row stride in bf16 units
#define ROW_B  1056              // act row stride in bytes

// ---------------- scratch (static __device__) -- keep total < 2GB ----------------
__device__ float  g_x0[(size_t)NROWS * NH];            // ~765 MB
__device__ float4 g_bp[8 * KS16 * 16 * 32];            // packed B fragments, 2 MB

// permuted bf16 position within a row for global k (16-groups, pairs interleaved
// so that k-pairs (2tig) and (2tig+8) are adjacent -> one LDS.64 per A frag pair)
__device__ __forceinline__ int bpos(int k) {
    int grp = k & ~15, q = k & 15, pj = q >> 1;
    int pp = (pj < 4) ? 2 * pj : 2 * pj - 7;
    return grp + 2 * pp + (q & 1);
}

__device__ __forceinline__ float sigf(float x) { return 1.0f / (1.0f + __expf(-x)); }

__device__ __forceinline__ unsigned bfpack2(float lo, float hi) {
    unsigned short a = __bfloat16_as_ushort(__float2bfloat16_rn(lo));
    unsigned short b = __bfloat16_as_ushort(__float2bfloat16_rn(hi));
    return (unsigned)a | ((unsigned)b << 16);
}

// m16n8k16 bf16 mma, f32 accum. a1 = row+8 / same k (R4 lesson).
__device__ __forceinline__ void mma16(float& c0, float& c1, float& c2, float& c3,
                                      unsigned a0, unsigned a1, unsigned a2, unsigned a3,
                                      unsigned b0, unsigned b1) {
    asm("mma.sync.aligned.m16n8k16.row.col.f32.bf16.bf16.f32 "
        "{%0,%1,%2,%3},{%4,%5,%6,%7},{%8,%9},{%0,%1,%2,%3};"
        : "+f"(c0), "+f"(c1), "+f"(c2), "+f"(c3)
        : "r"(a0), "r"(a1), "r"(a2), "r"(a3), "r"(b0), "r"(b1));
}

// ---------------- kernel 0: pack B fragments (hi/lo bf16) ----------------
// index bits: lane[0:5) ns[5:9) ks[9:14) w[14:17)
__global__ void pack_weights(const float* __restrict__ w_ih,
                             const float* __restrict__ w_hh) {
    int idx = blockIdx.x * 256 + threadIdx.x;        // 0..131071
    int lane = idx & 31, ns = (idx >> 5) & 15, ks = (idx >> 9) & 31, w = idx >> 14;
    int g0 = lane >> 2, tig = lane & 3;
    int col = w * 128 + ns * 8 + g0;
    int u = col >> 2, gate = col & 3;
    int jrow = gate * NH + u;
    float v[4]; float hi[4]; float lo[4];
#pragma unroll
    for (int e = 0; e < 4; e++) {
        int k = ks * 16 + 2 * tig + (e & 1) + (e >> 1) * 8;
        v[e] = (k < NH) ? w_hh[jrow * NH + k] : w_ih[jrow * NH + k - NH];
        hi[e] = __bfloat162float(__float2bfloat16_rn(v[e]));
        lo[e] = v[e] - hi[e];
    }
    float4 r;
    r.x = __uint_as_float(bfpack2(hi[0], hi[1]));
    r.y = __uint_as_float(bfpack2(hi[2], hi[3]));
    r.z = __uint_as_float(bfpack2(lo[0], lo[1]));
    r.w = __uint_as_float(bfpack2(lo[2], lo[3]));
    g_bp[idx] = r;
}

// ---------------- kernel 1: x0 = relu(x @ w_in^T + b_in) ----------------
__global__ __launch_bounds__(256) void in_proj(const float* __restrict__ x,
                                               const float* __restrict__ w_in,
                                               const float* __restrict__ b_in) {
    __shared__ float ws[NX][NH];
    __shared__ float xs[16][NX];
    int tid = threadIdx.x;
    for (int i = tid; i < NH * NX; i += 256) {
        int u = i >> 4, k = i & 15;
        ws[k][u] = w_in[i];
    }
    size_t row0 = (size_t)blockIdx.x * 16;
    {
        int r = tid >> 4, k = tid & 15;
        xs[r][k] = x[(row0 + r) * NX + k];
    }
    __syncthreads();
    int u = tid;
    float b = b_in[u];
#pragma unroll 4
    for (int r = 0; r < 16; r++) {
        float s = b;
#pragma unroll
        for (int k = 0; k < NX; k++) s = fmaf(xs[r][k], ws[k][u], s);
        g_x0[(row0 + r) * NH + u] = fmaxf(s, 0.0f);
    }
}

// ---------------- kernel 2: persistent fused LSTM scan, bf16x3 mma ----------------
// 64 CTAs x 256 threads (8 warps). CTA owns 32 rows (two m16 groups); each warp
// loads its B fragments ONCE per k-tile and feeds BOTH groups -> chip L2 weight
// traffic halves vs 16-row version. Warp w owns gate-interleaved N-slice
// [128w,128w+128). 3 passes: hi*hi + hi*lo + lo*hi.
__global__ __launch_bounds__(256, 1) void lstm_scan(const float* __restrict__ b_ih,
                                                    const float* __restrict__ b_hh,
                                                    const float* __restrict__ w_out,
                                                    const float* __restrict__ b_out,
                                                    float* __restrict__ out) {
    extern __shared__ unsigned smemu[];
    // bytes: actH [32*ROW_B], actL [32*ROW_B]; words: bias[1024], wout[256], outp[256]
    const int ALW = MROWS * ROW_B / 4;
    const int BI = 2 * MROWS * ROW_B / 4, WO = BI + 1024, OP = WO + 256;
    float* biasf = (float*)&smemu[BI];
    float* woutf = (float*)&smemu[WO];
    float* outpf = (float*)&smemu[OP];
    unsigned short* aH = (unsigned short*)&smemu[0];
    unsigned short* aL = (unsigned short*)&smemu[ALW];
    const char* cH = (const char*)&smemu[0];
    const char* cL = (const char*)&smemu[ALW];

    const int tid = threadIdx.x;
    const int w = tid >> 5, lane = tid & 31;
    const int g0 = lane >> 2, tig = lane & 3;
    const size_t row0 = (size_t)blockIdx.x * MROWS;
    const float b_out0 = b_out[0];

    for (int j = tid; j < G4; j += 256)
        biasf[j] = b_ih[(j & 3) * NH + (j >> 2)] + b_hh[(j & 3) * NH + (j >> 2)];
    woutf[tid] = w_out[tid];
    for (int i = tid; i < 2 * MROWS * (ROW_B / 4); i += 256) smemu[i] = 0u;
    __syncthreads();
    {   // x0(t=0): thread handles row=tid&31, 32 consecutive x-units
        int r = tid & 31, jb = (tid >> 5) * 32;
        const float* src = &g_x0[(row0 + r) * NH + jb];
#pragma unroll
        for (int i = 0; i < 32; i++) {
            int colp = bpos(NH + jb + i);
            float v = src[i];
            float hv = __bfloat162float(__float2bfloat16_rn(v));
            aH[r * ROW_BF + colp] = __bfloat16_as_ushort(__float2bfloat16_rn(v));
            aL[r * ROW_BF + colp] = __bfloat16_as_ushort(__float2bfloat16_rn(v - hv));
        }
    }
    float cst0[16], cst1[16];
#pragma unroll
    for (int i = 0; i < 16; i++) { cst0[i] = 0.0f; cst1[i] = 0.0f; }
    __syncthreads();

    const float4* __restrict__ Bw = g_bp + (size_t)w * (KS16 * 16 * 32) + lane;
    const int myrow = g0 + 8 * (tig & 1);
    const int aoff = tig * 8;

    for (int t = 0; t < NT; t++) {
        // finalize out(t-1)
        if (t > 0 && tid < MROWS) {
            float s = b_out0;
#pragma unroll
            for (int q = 0; q < 8; q++) s += outpf[tid * 8 + q];
            out[(size_t)(t - 1) * NGRID + row0 + tid] = s;
        }

        // accumulators: group A = rows 0-15, group B = rows 16-31
        float A0[16], A1[16], A2[16], A3[16];
        float B0[16], B1[16], B2[16], B3[16];
#pragma unroll
        for (int i = 0; i < 16; i++) {
            A0[i] = 0.f; A1[i] = 0.f; A2[i] = 0.f; A3[i] = 0.f;
            B0[i] = 0.f; B1[i] = 0.f; B2[i] = 0.f; B3[i] = 0.f;
        }

#pragma unroll 1
        for (int ks = 0; ks < KS16; ks++) {
            // A fragments for both row groups
            uint2 h0a = *(const uint2*)(cH + g0 * ROW_B + ks * 32 + aoff);
            uint2 h0b = *(const uint2*)(cH + (g0 + 8) * ROW_B + ks * 32 + aoff);
            uint2 l0a = *(const uint2*)(cL + g0 * ROW_B + ks * 32 + aoff);
            uint2 l0b = *(const uint2*)(cL + (g0 + 8) * ROW_B + ks * 32 + aoff);
            uint2 h1a = *(const uint2*)(cH + (16 + g0) * ROW_B + ks * 32 + aoff);
            uint2 h1b = *(const uint2*)(cH + (24 + g0) * ROW_B + ks * 32 + aoff);
            uint2 l1a = *(const uint2*)(cL + (16 + g0) * ROW_B + ks * 32 + aoff);
            uint2 l1b = *(const uint2*)(cL + (24 + g0) * ROW_B + ks * 32 + aoff);
#pragma unroll
            for (int half = 0; half < 2; half++) {
                float4 b[8];
#pragma unroll
                for (int j = 0; j < 8; j++) b[j] = Bw[ks * 512 + (half * 8 + j) * 32];
#pragma unroll
                for (int j = 0; j < 8; j++) {
                    int ns = half * 8 + j;
                    unsigned bh0 = __float_as_uint(b[j].x), bh1 = __float_as_uint(b[j].y);
                    unsigned bl0 = __float_as_uint(b[j].z), bl1 = __float_as_uint(b[j].w);
                    mma16(A0[ns], A1[ns], A2[ns], A3[ns], h0a.x, h0b.x, h0a.y, h0b.y, bh0, bh1);
                    mma16(A0[ns], A1[ns], A2[ns], A3[ns], h0a.x, h0b.x, h0a.y, h0b.y, bl0, bl1);
                    mma16(A0[ns], A1[ns], A2[ns], A3[ns], l0a.x, l0b.x, l0a.y, l0b.y, bh0, bh1);
                    mma16(B0[ns], B1[ns], B2[ns], B3[ns], h1a.x, h1b.x, h1a.y, h1b.y, bh0, bh1);
                    mma16(B0[ns], B1[ns], B2[ns], B3[ns], h1a.x, h1b.x, h1a.y, h1b.y, bl0, bl1);
                    mma16(B0[ns], B1[ns], B2[ns], B3[ns], l1a.x, l1b.x, l1a.y, l1b.y, bh0, bh1);
                }
            }
        }
        __syncthreads();   // all act reads done

        // prefetch x0(t+1) for this thread's slice (32 floats)
        float4 xv[8];
        int xr = tid & 31, xjb = (tid >> 5) * 32;
        if (t + 1 < NT) {
            const float4* src =
                (const float4*)&g_x0[((size_t)(t + 1) * NGRID + row0 + xr) * NH + xjb];
#pragma unroll
            for (int q = 0; q < 8; q++) xv[q] = src[q];
        }

        // gates -> h,c per group ; write h(t) ; accumulate out partial
#pragma unroll
        for (int grp = 0; grp < 2; grp++) {
            float partial = 0.0f;
            int row = grp * 16 + myrow;
#pragma unroll
            for (int ns = 0; ns < 16; ns++) {
                float c0 = grp ? B0[ns] : A0[ns];
                float c1 = grp ? B1[ns] : A1[ns];
                float c2 = grp ? B2[ns] : A2[ns];
                float c3 = grp ? B3[ns] : A3[ns];
                float s0 = (tig & 1) ? c0 : c2;
                float s1 = (tig & 1) ? c1 : c3;
                float r0 = __shfl_xor_sync(0xffffffffu, s0, 1);
                float r1 = __shfl_xor_sync(0xffffffffu, s1, 1);
                float gi, gf, gg, go;
                if ((tig & 1) == 0) { gi = c0; gf = c1; gg = r0; go = r1; }
                else                { gi = r0; gf = r1; gg = c2; go = c3; }
                int ug = w * 32 + 2 * ns + (tig >> 1);
                float4 bs = *(const float4*)&biasf[ug * 4];
                float iv = sigf(gi + bs.x);
                float fv = sigf(gf + bs.y);
                float gv = tanhf(gg + bs.z);
                float ov = sigf(go + bs.w);
                float cold = grp ? cst1[ns] : cst0[ns];
                float c = fmaf(fv, cold, iv * gv);
                if (grp) cst1[ns] = c; else cst0[ns] = c;
                float h = ov * tanhf(c);
                partial = fmaf(h, woutf[ug], partial);
                int colp = bpos(ug);
                float hv = __bfloat162float(__float2bfloat16_rn(h));
                aH[row * ROW_BF + colp] = __bfloat16_as_ushort(__float2bfloat16_rn(h));
                aL[row * ROW_BF + colp] = __bfloat16_as_ushort(__float2bfloat16_rn(h - hv));
            }
            partial += __shfl_xor_sync(0xffffffffu, partial, 2);
            if (tig < 2) outpf[row * 8 + w] = partial;
        }

        // store x0(t+1) bf16 hi/lo
        if (t + 1 < NT) {
            const float* xf = (const float*)xv;
#pragma unroll
            for (int i = 0; i < 32; i++) {
                int colp = bpos(NH + xjb + i);
                float v = xf[i];
                float hv = __bfloat162float(__float2bfloat16_rn(v));
                aH[xr * ROW_BF + colp] = __bfloat16_as_ushort(__float2bfloat16_rn(v));
                aL[xr * ROW_BF + colp] = __bfloat16_as_ushort(__float2bfloat16_rn(v - hv));
            }
        }
        __syncthreads();   // act(t+1) ready
    }
    // final timestep output
    if (tid < MROWS) {
        float s = b_out0;
#pragma unroll
        for (int q = 0; q < 8; q++) s += outpf[tid * 8 + q];
        out[(size_t)(NT - 1) * NGRID + row0 + tid] = s;
    }
}

// ---------------- launch ----------------
extern "C" void kernel_launch(void* const* d_in, const int* in_sizes, int n_in,
                              void* d_out, int out_size) {
    const float* x     = (const float*)d_in[0];
    const float* w_in  = (const float*)d_in[1];
    const float* b_in  = (const float*)d_in[2];
    const float* w_ih  = (const float*)d_in[3];
    const float* w_hh  = (const float*)d_in[4];
    const float* b_ih  = (const float*)d_in[5];
    const float* b_hh  = (const float*)d_in[6];
    const float* w_out = (const float*)d_in[7];
    const float* b_out = (const float*)d_in[8];
    float* out = (float*)d_out;

    const int smem_scan = 2 * MROWS * ROW_B + (1024 + 256 + 256) * (int)sizeof(float);
    cudaFuncSetAttribute(lstm_scan, cudaFuncAttributeMaxDynamicSharedMemorySize,
                         smem_scan);

    pack_weights<<<512, 256>>>(w_ih, w_hh);
    in_proj<<<NROWS / 16, 256>>>(x, w_in, b_in);
    lstm_scan<<<NGRID / MROWS, 256, smem_scan>>>(b_ih, b_hh, w_out, b_out, out);
}

// round 9
// speedup vs baseline: 2.5694x; 2.5694x over previous
#include <cuda_runtime.h>
#include <cuda_fp16.h>
#include <math.h>

#define NT     365
#define NGRID  2048
#define NX     16
#define NH     256
#define G4     1024              // 4*NH
#define K2     512               // combined k = NH (h) + NH (x0)
#define NROWS  (NT * NGRID)      // 747520
#define KS16   32                // K2/16 k-tiles
#define ROW_BF 528               // act row stride in fp16 units
#define ROW_B  1056              // act row stride in bytes

// ---------------- scratch (static __device__) -- keep total < 2GB ----------------
__device__ float g_x0[(size_t)NROWS * NH];             // ~765 MB
__device__ uint2 g_bp[8 * KS16 * 16 * 32];             // packed B_hi fragments, 1 MB

// permuted fp16 position within a row for global k (16-groups, pairs interleaved
// so that k-pairs (2tig) and (2tig+8) are adjacent -> one LDS.64 per A frag pair)
__device__ __forceinline__ int bpos(int k) {
    int grp = k & ~15, q = k & 15, pj = q >> 1;
    int pp = (pj < 4) ? 2 * pj : 2 * pj - 7;
    return grp + 2 * pp + (q & 1);
}

__device__ __forceinline__ float sigf(float x) { return 1.0f / (1.0f + __expf(-x)); }

__device__ __forceinline__ unsigned hpack2(float lo, float hi) {
    __half2 h = __floats2half2_rn(lo, hi);
    return *(unsigned*)&h;
}

// m16n8k16 fp16 mma, f32 accum. a1 = row+8 / same k (R4 lesson).
__device__ __forceinline__ void mma16h(float& c0, float& c1, float& c2, float& c3,
                                       unsigned a0, unsigned a1, unsigned a2, unsigned a3,
                                       unsigned b0, unsigned b1) {
    asm("mma.sync.aligned.m16n8k16.row.col.f32.f16.f16.f32 "
        "{%0,%1,%2,%3},{%4,%5,%6,%7},{%8,%9},{%0,%1,%2,%3};"
        : "+f"(c0), "+f"(c1), "+f"(c2), "+f"(c3)
        : "r"(a0), "r"(a1), "r"(a2), "r"(a3), "r"(b0), "r"(b1));
}

// ---------------- kernel 0: pack B_hi fragments (fp16) ----------------
// B[k][col]: col=(u<<2)|gate; k<256 -> w_hh[gate*NH+u][k], else w_ih[...][k-256]
// frag (w,ks,ns,lane): b0 = k-pair (16ks+2tig, +1), b1 = (16ks+2tig+8, +9), col=128w+8ns+g0
// index bits: lane[0:5) ns[5:9) ks[9:14) w[14:17)
__global__ void pack_weights(const float* __restrict__ w_ih,
                             const float* __restrict__ w_hh) {
    int idx = blockIdx.x * 256 + threadIdx.x;        // 0..131071
    int lane = idx & 31, ns = (idx >> 5) & 15, ks = (idx >> 9) & 31, w = idx >> 14;
    int g0 = lane >> 2, tig = lane & 3;
    int col = w * 128 + ns * 8 + g0;
    int u = col >> 2, gate = col & 3;
    int jrow = gate * NH + u;
    float v[4];
#pragma unroll
    for (int e = 0; e < 4; e++) {
        int k = ks * 16 + 2 * tig + (e & 1) + (e >> 1) * 8;
        v[e] = (k < NH) ? w_hh[jrow * NH + k] : w_ih[jrow * NH + k - NH];
    }
    uint2 r;
    r.x = hpack2(v[0], v[1]);
    r.y = hpack2(v[2], v[3]);
    g_bp[idx] = r;
}

// ---------------- kernel 1: x0 = relu(x @ w_in^T + b_in) ----------------
__global__ __launch_bounds__(256) void in_proj(const float* __restrict__ x,
                                               const float* __restrict__ w_in,
                                               const float* __restrict__ b_in) {
    __shared__ float ws[NX][NH];
    __shared__ float xs[16][NX];
    int tid = threadIdx.x;
    for (int i = tid; i < NH * NX; i += 256) {
        int u = i >> 4, k = i & 15;
        ws[k][u] = w_in[i];
    }
    size_t row0 = (size_t)blockIdx.x * 16;
    {
        int r = tid >> 4, k = tid & 15;
        xs[r][k] = x[(row0 + r) * NX + k];
    }
    __syncthreads();
    int u = tid;
    float b = b_in[u];
#pragma unroll 4
    for (int r = 0; r < 16; r++) {
        float s = b;
#pragma unroll
        for (int k = 0; k < NX; k++) s = fmaf(xs[r][k], ws[k][u], s);
        g_x0[(row0 + r) * NH + u] = fmaxf(s, 0.0f);
    }
}

// ---------------- kernel 2: persistent fused LSTM scan, fp16 2-pass mma ----------------
// 128 CTAs x 256 threads (8 warps). CTA owns 16 rows. Warp w owns gate-interleaved
// N-slice [128w,128w+128). A = [16 rows][512 k] act (h|x0), fp16 hi+lo planes in
// SMEM. 2 passes: a_hi*b_hi + a_lo*b_hi  (missing a*b_lo ~ 2^-12 rel).
__global__ __launch_bounds__(256, 1) void lstm_scan(const float* __restrict__ b_ih,
                                                    const float* __restrict__ b_hh,
                                                    const float* __restrict__ w_out,
                                                    const float* __restrict__ b_out,
                                                    float* __restrict__ out) {
    extern __shared__ unsigned smemu[];
    // bytes: actH [16*ROW_B], actL [16*ROW_B]; words: bias[1024], wout[256], outp[128]
    const int ALW = 16 * ROW_B / 4;
    const int BI = 2 * 16 * ROW_B / 4, WO = BI + 1024, OP = WO + 256;
    float* biasf = (float*)&smemu[BI];
    float* woutf = (float*)&smemu[WO];
    float* outpf = (float*)&smemu[OP];
    __half* aH = (__half*)&smemu[0];
    __half* aL = (__half*)&smemu[ALW];
    const char* cH = (const char*)&smemu[0];
    const char* cL = (const char*)&smemu[ALW];

    const int tid = threadIdx.x;
    const int w = tid >> 5, lane = tid & 31;
    const int g0 = lane >> 2, tig = lane & 3;
    const size_t row0 = (size_t)blockIdx.x * 16;
    const float b_out0 = b_out[0];

    for (int j = tid; j < G4; j += 256)
        biasf[j] = b_ih[(j & 3) * NH + (j >> 2)] + b_hh[(j & 3) * NH + (j >> 2)];
    woutf[tid] = w_out[tid];
    for (int i = tid; i < 2 * 16 * (ROW_B / 4); i += 256) smemu[i] = 0u;
    __syncthreads();
    {   // x0(t=0): thread handles row=tid&15, 16 consecutive x-units
        int r = tid & 15, jb = (tid >> 4) * 16;
        const float* src = &g_x0[(row0 + r) * NH + jb];
#pragma unroll
        for (int i = 0; i < 16; i++) {
            int colp = bpos(NH + jb + i);
            float v = src[i];
            __half hv = __float2half_rn(v);
            aH[r * ROW_BF + colp] = hv;
            aL[r * ROW_BF + colp] = __float2half_rn(v - __half2float(hv));
        }
    }
    float cst[16];
#pragma unroll
    for (int i = 0; i < 16; i++) cst[i] = 0.0f;
    __syncthreads();

    const uint2* __restrict__ Bw = g_bp + (size_t)w * (KS16 * 16 * 32) + lane;
    const int myrow = g0 + 8 * (tig & 1);
    const int aoff = tig * 8;   // byte offset within k-tile for this lane's A frags

    for (int t = 0; t < NT; t++) {
        // finalize out(t-1)
        if (t > 0 && tid < 16) {
            float s = b_out0;
#pragma unroll
            for (int q = 0; q < 8; q++) s += outpf[tid * 8 + q];
            out[(size_t)(t - 1) * NGRID + row0 + tid] = s;
        }

        float C0[16], C1[16], C2[16], C3[16];
#pragma unroll
        for (int i = 0; i < 16; i++) { C0[i] = 0.f; C1[i] = 0.f; C2[i] = 0.f; C3[i] = 0.f; }

        uint2 bcur[16];
#pragma unroll
        for (int ns = 0; ns < 16; ns++) bcur[ns] = Bw[ns * 32];

#pragma unroll 1
        for (int ks = 0; ks < KS16; ks++) {
            uint2 bnxt[16];
            int ks2 = (ks + 1) & (KS16 - 1);   // wrap: last-iter loads dead but in-bounds
#pragma unroll
            for (int ns = 0; ns < 16; ns++) bnxt[ns] = Bw[ks2 * 512 + ns * 32];

            uint2 h_r0 = *(const uint2*)(cH + g0 * ROW_B + ks * 32 + aoff);
            uint2 h_r8 = *(const uint2*)(cH + (g0 + 8) * ROW_B + ks * 32 + aoff);
            uint2 l_r0 = *(const uint2*)(cL + g0 * ROW_B + ks * 32 + aoff);
            uint2 l_r8 = *(const uint2*)(cL + (g0 + 8) * ROW_B + ks * 32 + aoff);
#pragma unroll
            for (int ns = 0; ns < 16; ns++) {
                mma16h(C0[ns], C1[ns], C2[ns], C3[ns],
                       h_r0.x, h_r8.x, h_r0.y, h_r8.y, bcur[ns].x, bcur[ns].y);
                mma16h(C0[ns], C1[ns], C2[ns], C3[ns],
                       l_r0.x, l_r8.x, l_r0.y, l_r8.y, bcur[ns].x, bcur[ns].y);
            }
#pragma unroll
            for (int ns = 0; ns < 16; ns++) bcur[ns] = bnxt[ns];
        }
        __syncthreads();   // all act reads done

        // prefetch x0(t+1) for this thread's slice
        float4 xv[4];
        int xr = tid & 15, xjb = (tid >> 4) * 16;
        if (t + 1 < NT) {
            const float4* src =
                (const float4*)&g_x0[((size_t)(t + 1) * NGRID + row0 + xr) * NH + xjb];
#pragma unroll
            for (int q = 0; q < 4; q++) xv[q] = src[q];
        }

        // gates -> h,c ; write h(t) fp16 hi/lo into act ; accumulate out partial
        float partial = 0.0f;
#pragma unroll
        for (int ns = 0; ns < 16; ns++) {
            float s0 = (tig & 1) ? C0[ns] : C2[ns];
            float s1 = (tig & 1) ? C1[ns] : C3[ns];
            float r0 = __shfl_xor_sync(0xffffffffu, s0, 1);
            float r1 = __shfl_xor_sync(0xffffffffu, s1, 1);
            float gi, gf, gg, go;
            if ((tig & 1) == 0) { gi = C0[ns]; gf = C1[ns]; gg = r0; go = r1; }
            else                { gi = r0;     gf = r1;     gg = C2[ns]; go = C3[ns]; }
            int ug = w * 32 + 2 * ns + (tig >> 1);
            float4 bs = *(const float4*)&biasf[ug * 4];
            float iv = sigf(gi + bs.x);
            float fv = sigf(gf + bs.y);
            float gv = tanhf(gg + bs.z);
            float ov = sigf(go + bs.w);
            float c = fmaf(fv, cst[ns], iv * gv);
            cst[ns] = c;
            float h = ov * tanhf(c);
            partial = fmaf(h, woutf[ug], partial);
            int colp = bpos(ug);
            __half hv = __float2half_rn(h);
            aH[myrow * ROW_BF + colp] = hv;
            aL[myrow * ROW_BF + colp] = __float2half_rn(h - __half2float(hv));
        }
        partial += __shfl_xor_sync(0xffffffffu, partial, 2);
        if (tig < 2) outpf[myrow * 8 + w] = partial;

        // store x0(t+1) fp16 hi/lo
        if (t + 1 < NT) {
            const float* xf = (const float*)xv;
#pragma unroll
            for (int i = 0; i < 16; i++) {
                int colp = bpos(NH + xjb + i);
                float v = xf[i];
                __half hv = __float2half_rn(v);
                aH[xr * ROW_BF + colp] = hv;
                aL[xr * ROW_BF + colp] = __float2half_rn(v - __half2float(hv));
            }
        }
        __syncthreads();   // act(t+1) ready
    }
    // final timestep output
    if (tid < 16) {
        float s = b_out0;
#pragma unroll
        for (int q = 0; q < 8; q++) s += outpf[tid * 8 + q];
        out[(size_t)(NT - 1) * NGRID + row0 + tid] = s;
    }
}

// ---------------- launch ----------------
extern "C" void kernel_launch(void* const* d_in, const int* in_sizes, int n_in,
                              void* d_out, int out_size) {
    const float* x     = (const float*)d_in[0];
    const float* w_in  = (const float*)d_in[1];
    const float* b_in  = (const float*)d_in[2];
    const float* w_ih  = (const float*)d_in[3];
    const float* w_hh  = (const float*)d_in[4];
    const float* b_ih  = (const float*)d_in[5];
    const float* b_hh  = (const float*)d_in[6];
    const float* w_out = (const float*)d_in[7];
    const float* b_out = (const float*)d_in[8];
    float* out = (float*)d_out;

    const int smem_scan = 2 * 16 * ROW_B + (1024 + 256 + 128) * (int)sizeof(float);
    cudaFuncSetAttribute(lstm_scan, cudaFuncAttributeMaxDynamicSharedMemorySize,
                         smem_scan);

    pack_weights<<<512, 256>>>(w_ih, w_hh);
    in_proj<<<NROWS / 16, 256>>>(x, w_in, b_in);
    lstm_scan<<<NGRID / 16, 256, smem_scan>>>(b_ih, b_hh, w_out, b_out, out);
}

// round 10
// speedup vs baseline: 2.7043x; 1.0525x over previous
#include <cuda_runtime.h>
#include <cuda_fp16.h>
#include <math.h>

#define NT     365
#define NGRID  2048
#define NX     16
#define NH     256
#define G4     1024              // 4*NH
#define K2     512               // combined k = NH (h) + NH (x0)
#define NROWS  (NT * NGRID)      // 747520
#define KS16   32                // K2/16 k-tiles (0..15 = h half, 16..31 = x half)
#define ROW_BF 528               // act row stride in fp16 units
#define ROW_B  1056              // act row stride in bytes

// ---------------- scratch (static __device__) -- keep total < 2GB ----------------
__device__ float g_x0[(size_t)NROWS * NH];             // ~765 MB
__device__ uint2 g_bp[8 * KS16 * 16 * 32];             // packed B_hi fragments, 1 MB

// permuted fp16 position within a row for global k (16-groups, pairs interleaved
// so that k-pairs (2tig) and (2tig+8) are adjacent -> one LDS.64 per A frag pair)
__device__ __forceinline__ int bpos(int k) {
    int grp = k & ~15, q = k & 15, pj = q >> 1;
    int pp = (pj < 4) ? 2 * pj : 2 * pj - 7;
    return grp + 2 * pp + (q & 1);
}

__device__ __forceinline__ float sigf(float x) { return 1.0f / (1.0f + __expf(-x)); }

__device__ __forceinline__ unsigned hpack2(float lo, float hi) {
    __half2 h = __floats2half2_rn(lo, hi);
    return *(unsigned*)&h;
}

// m16n8k16 fp16 mma, f32 accum. a1 = row+8 / same k (R4 lesson).
__device__ __forceinline__ void mma16h(float& c0, float& c1, float& c2, float& c3,
                                       unsigned a0, unsigned a1, unsigned a2, unsigned a3,
                                       unsigned b0, unsigned b1) {
    asm("mma.sync.aligned.m16n8k16.row.col.f32.f16.f16.f32 "
        "{%0,%1,%2,%3},{%4,%5,%6,%7},{%8,%9},{%0,%1,%2,%3};"
        : "+f"(c0), "+f"(c1), "+f"(c2), "+f"(c3)
        : "r"(a0), "r"(a1), "r"(a2), "r"(a3), "r"(b0), "r"(b1));
}

// ---------------- kernel 0: pack B_hi fragments (fp16) ----------------
// B[k][col]: col=(u<<2)|gate; k<256 -> w_hh[gate*NH+u][k], else w_ih[...][k-256]
// frag (w,ks,ns,lane): b0 = k-pair (16ks+2tig, +1), b1 = (16ks+2tig+8, +9), col=128w+8ns+g0
// index bits: lane[0:5) ns[5:9) ks[9:14) w[14:17)
__global__ void pack_weights(const float* __restrict__ w_ih,
                             const float* __restrict__ w_hh) {
    int idx = blockIdx.x * 256 + threadIdx.x;        // 0..131071
    int lane = idx & 31, ns = (idx >> 5) & 15, ks = (idx >> 9) & 31, w = idx >> 14;
    int g0 = lane >> 2, tig = lane & 3;
    int col = w * 128 + ns * 8 + g0;
    int u = col >> 2, gate = col & 3;
    int jrow = gate * NH + u;
    float v[4];
#pragma unroll
    for (int e = 0; e < 4; e++) {
        int k = ks * 16 + 2 * tig + (e & 1) + (e >> 1) * 8;
        v[e] = (k < NH) ? w_hh[jrow * NH + k] : w_ih[jrow * NH + k - NH];
    }
    uint2 r;
    r.x = hpack2(v[0], v[1]);
    r.y = hpack2(v[2], v[3]);
    g_bp[idx] = r;
}

// ---------------- kernel 1: x0 = relu(x @ w_in^T + b_in) ----------------
__global__ __launch_bounds__(256) void in_proj(const float* __restrict__ x,
                                               const float* __restrict__ w_in,
                                               const float* __restrict__ b_in) {
    __shared__ float ws[NX][NH];
    __shared__ float xs[16][NX];
    int tid = threadIdx.x;
    for (int i = tid; i < NH * NX; i += 256) {
        int u = i >> 4, k = i & 15;
        ws[k][u] = w_in[i];
    }
    size_t row0 = (size_t)blockIdx.x * 16;
    {
        int r = tid >> 4, k = tid & 15;
        xs[r][k] = x[(row0 + r) * NX + k];
    }
    __syncthreads();
    int u = tid;
    float b = b_in[u];
#pragma unroll 4
    for (int r = 0; r < 16; r++) {
        float s = b;
#pragma unroll
        for (int k = 0; k < NX; k++) s = fmaf(xs[r][k], ws[k][u], s);
        g_x0[(row0 + r) * NH + u] = fmaxf(s, 0.0f);
    }
}

// ---------------- kernel 2: persistent fused LSTM scan, fp16 1.5-pass mma ----------------
// 128 CTAs x 256 threads (8 warps). CTA owns 16 rows. Warp w owns gate-interleaved
// N-slice [128w,128w+128). A = [16 rows][512 k] act (h|x0), fp16 hi (+lo for h half)
// in SMEM. h half (ks<16): a_hi*b + a_lo*b (recurrent -> needs compensation);
// x half (ks>=16): a_hi*b only (non-recurrent, error enters once per step).
__global__ __launch_bounds__(256, 1) void lstm_scan(const float* __restrict__ b_ih,
                                                    const float* __restrict__ b_hh,
                                                    const float* __restrict__ w_out,
                                                    const float* __restrict__ b_out,
                                                    float* __restrict__ out) {
    extern __shared__ unsigned smemu[];
    // bytes: actH [16*ROW_B], actL [16*ROW_B]; words: bias[1024], wout[256], outp[128]
    const int ALW = 16 * ROW_B / 4;
    const int BI = 2 * 16 * ROW_B / 4, WO = BI + 1024, OP = WO + 256;
    float* biasf = (float*)&smemu[BI];
    float* woutf = (float*)&smemu[WO];
    float* outpf = (float*)&smemu[OP];
    __half* aH = (__half*)&smemu[0];
    __half* aL = (__half*)&smemu[ALW];
    const char* cH = (const char*)&smemu[0];
    const char* cL = (const char*)&smemu[ALW];

    const int tid = threadIdx.x;
    const int w = tid >> 5, lane = tid & 31;
    const int g0 = lane >> 2, tig = lane & 3;
    const size_t row0 = (size_t)blockIdx.x * 16;
    const float b_out0 = b_out[0];

    for (int j = tid; j < G4; j += 256)
        biasf[j] = b_ih[(j & 3) * NH + (j >> 2)] + b_hh[(j & 3) * NH + (j >> 2)];
    woutf[tid] = w_out[tid];
    for (int i = tid; i < 2 * 16 * (ROW_B / 4); i += 256) smemu[i] = 0u;
    __syncthreads();
    {   // x0(t=0): thread handles row=tid&15, 16 consecutive x-units (hi only)
        int r = tid & 15, jb = (tid >> 4) * 16;
        const float* src = &g_x0[(row0 + r) * NH + jb];
#pragma unroll
        for (int i = 0; i < 16; i++) {
            int colp = bpos(NH + jb + i);
            aH[r * ROW_BF + colp] = __float2half_rn(src[i]);
        }
    }
    float cst[16];
#pragma unroll
    for (int i = 0; i < 16; i++) cst[i] = 0.0f;
    __syncthreads();

    const uint2* __restrict__ Bw = g_bp + (size_t)w * (KS16 * 16 * 32) + lane;
    const int myrow = g0 + 8 * (tig & 1);
    const int aoff = tig * 8;   // byte offset within k-tile for this lane's A frags

    for (int t = 0; t < NT; t++) {
        // finalize out(t-1)
        if (t > 0 && tid < 16) {
            float s = b_out0;
#pragma unroll
            for (int q = 0; q < 8; q++) s += outpf[tid * 8 + q];
            out[(size_t)(t - 1) * NGRID + row0 + tid] = s;
        }

        float C0[16], C1[16], C2[16], C3[16];
#pragma unroll
        for (int i = 0; i < 16; i++) { C0[i] = 0.f; C1[i] = 0.f; C2[i] = 0.f; C3[i] = 0.f; }

        uint2 bcur[16];
#pragma unroll
        for (int ns = 0; ns < 16; ns++) bcur[ns] = Bw[ns * 32];

#pragma unroll 1
        for (int ks = 0; ks < KS16; ks++) {
            uint2 bnxt[16];
            int ks2 = (ks + 1) & (KS16 - 1);   // wrap: last-iter loads dead but in-bounds
#pragma unroll
            for (int ns = 0; ns < 16; ns++) bnxt[ns] = Bw[ks2 * 512 + ns * 32];

            uint2 h_r0 = *(const uint2*)(cH + g0 * ROW_B + ks * 32 + aoff);
            uint2 h_r8 = *(const uint2*)(cH + (g0 + 8) * ROW_B + ks * 32 + aoff);
            if (ks < 16) {   // h half: hi + lo passes
                uint2 l_r0 = *(const uint2*)(cL + g0 * ROW_B + ks * 32 + aoff);
                uint2 l_r8 = *(const uint2*)(cL + (g0 + 8) * ROW_B + ks * 32 + aoff);
#pragma unroll
                for (int ns = 0; ns < 16; ns++) {
                    mma16h(C0[ns], C1[ns], C2[ns], C3[ns],
                           h_r0.x, h_r8.x, h_r0.y, h_r8.y, bcur[ns].x, bcur[ns].y);
                    mma16h(C0[ns], C1[ns], C2[ns], C3[ns],
                           l_r0.x, l_r8.x, l_r0.y, l_r8.y, bcur[ns].x, bcur[ns].y);
                }
            } else {         // x half: hi pass only
#pragma unroll
                for (int ns = 0; ns < 16; ns++) {
                    mma16h(C0[ns], C1[ns], C2[ns], C3[ns],
                           h_r0.x, h_r8.x, h_r0.y, h_r8.y, bcur[ns].x, bcur[ns].y);
                }
            }
#pragma unroll
            for (int ns = 0; ns < 16; ns++) bcur[ns] = bnxt[ns];
        }
        __syncthreads();   // all act reads done

        // prefetch x0(t+1) for this thread's slice
        float4 xv[4];
        int xr = tid & 15, xjb = (tid >> 4) * 16;
        if (t + 1 < NT) {
            const float4* src =
                (const float4*)&g_x0[((size_t)(t + 1) * NGRID + row0 + xr) * NH + xjb];
#pragma unroll
            for (int q = 0; q < 4; q++) xv[q] = src[q];
        }

        // gates -> h,c ; write h(t) fp16 hi/lo into act ; accumulate out partial
        float partial = 0.0f;
#pragma unroll
        for (int ns = 0; ns < 16; ns++) {
            float s0 = (tig & 1) ? C0[ns] : C2[ns];
            float s1 = (tig & 1) ? C1[ns] : C3[ns];
            float r0 = __shfl_xor_sync(0xffffffffu, s0, 1);
            float r1 = __shfl_xor_sync(0xffffffffu, s1, 1);
            float gi, gf, gg, go;
            if ((tig & 1) == 0) { gi = C0[ns]; gf = C1[ns]; gg = r0; go = r1; }
            else                { gi = r0;     gf = r1;     gg = C2[ns]; go = C3[ns]; }
            int ug = w * 32 + 2 * ns + (tig >> 1);
            float4 bs = *(const float4*)&biasf[ug * 4];
            float iv = sigf(gi + bs.x);
            float fv = sigf(gf + bs.y);
            float gv = tanhf(gg + bs.z);
            float ov = sigf(go + bs.w);
            float c = fmaf(fv, cst[ns], iv * gv);
            cst[ns] = c;
            float h = ov * tanhf(c);
            partial = fmaf(h, woutf[ug], partial);
            int colp = bpos(ug);
            __half hv = __float2half_rn(h);
            aH[myrow * ROW_BF + colp] = hv;
            aL[myrow * ROW_BF + colp] = __float2half_rn(h - __half2float(hv));
        }
        partial += __shfl_xor_sync(0xffffffffu, partial, 2);
        if (tig < 2) outpf[myrow * 8 + w] = partial;

        // store x0(t+1) fp16 hi only (x half runs single pass)
        if (t + 1 < NT) {
            const float* xf = (const float*)xv;
#pragma unroll
            for (int i = 0; i < 16; i++) {
                int colp = bpos(NH + xjb + i);
                aH[xr * ROW_BF + colp] = __float2half_rn(xf[i]);
            }
        }
        __syncthreads();   // act(t+1) ready
    }
    // final timestep output
    if (tid < 16) {
        float s = b_out0;
#pragma unroll
        for (int q = 0; q < 8; q++) s += outpf[tid * 8 + q];
        out[(size_t)(NT - 1) * NGRID + row0 + tid] = s;
    }
}

// ---------------- launch ----------------
extern "C" void kernel_launch(void* const* d_in, const int* in_sizes, int n_in,
                              void* d_out, int out_size) {
    const float* x     = (const float*)d_in[0];
    const float* w_in  = (const float*)d_in[1];
    const float* b_in  = (const float*)d_in[2];
    const float* w_ih  = (const float*)d_in[3];
    const float* w_hh  = (const float*)d_in[4];
    const float* b_ih  = (const float*)d_in[5];
    const float* b_hh  = (const float*)d_in[6];
    const float* w_out = (const float*)d_in[7];
    const float* b_out = (const float*)d_in[8];
    float* out = (float*)d_out;

    const int smem_scan = 2 * 16 * ROW_B + (1024 + 256 + 128) * (int)sizeof(float);
    cudaFuncSetAttribute(lstm_scan, cudaFuncAttributeMaxDynamicSharedMemorySize,
                         smem_scan);

    pack_weights<<<512, 256>>>(w_ih, w_hh);
    in_proj<<<NROWS / 16, 256>>>(x, w_in, b_in);
    lstm_scan<<<NGRID / 16, 256, smem_scan>>>(b_ih, b_hh, w_out, b_out, out);
}